// round 3
// baseline (speedup 1.0000x reference)
#include <cuda_runtime.h>
#include <cuda_bf16.h>
#include <math.h>

// ViT_15358803051012 — fully fused, one kernel.
// Block = 256 threads = 16 samples x 16 threads (thread t = output dim d).
// Warp = 2 samples (lanes 0-15 sample A, lanes 16-31 sample B).
//
// SMEM plan (floats):
//   PB  : [16][49*16] patches, later reused as tok2
//   V1  : [16][49*16] V1, later reused as tok3 (stride 8 within)
//   V2  : [16][49*8]
//   H   : [16][16] fc1 activations
//   LG  : [16][16] logits
//   PE  : [49*16] pos_emb
//   F1W : [16][396] fc1_w padded
//   F2W/F1B/F2B : small
//   WCH : per-7-patch weight chunk (layer1: 3*16 rows x 36 pad; layer2 reuses)

#define GRP 16        // samples per block
#define NTHR 256

// ---- smem layout (float offsets) ----
static constexpr int SM_PB  = 0;
static constexpr int SM_V1  = SM_PB  + GRP * 784;
static constexpr int SM_V2  = SM_V1  + GRP * 784;
static constexpr int SM_H   = SM_V2  + GRP * 392;
static constexpr int SM_LG  = SM_H   + GRP * 16;
static constexpr int SM_PE  = SM_LG  + GRP * 16;
static constexpr int SM_F1W = SM_PE  + 784;
static constexpr int SM_F2W = SM_F1W + 16 * 396;
static constexpr int SM_F1B = SM_F2W + 160;
static constexpr int SM_F2B = SM_F1B + 16;
static constexpr int SM_WCH = SM_F2B + 16;
static constexpr int WCH_SZ = 7 * 3 * 16 * 36;   // 12096 (layer1 chunk; layer2 fits inside)
static constexpr int SM_TOT = SM_WCH + WCH_SZ;   // 51280 floats = 205120 B

__device__ __forceinline__ float dot32_v4(const float* __restrict__ w, const float* tk) {
    float acc = 0.f;
#pragma unroll
    for (int i = 0; i < 8; i++) {
        float4 ww = *reinterpret_cast<const float4*>(w + 4 * i);
        acc = fmaf(tk[4 * i + 0], ww.x, acc);
        acc = fmaf(tk[4 * i + 1], ww.y, acc);
        acc = fmaf(tk[4 * i + 2], ww.z, acc);
        acc = fmaf(tk[4 * i + 3], ww.w, acc);
    }
    return acc;
}

__device__ __forceinline__ float dot16_v4(const float* __restrict__ w, const float* tk) {
    float acc = 0.f;
#pragma unroll
    for (int i = 0; i < 4; i++) {
        float4 ww = *reinterpret_cast<const float4*>(w + 4 * i);
        acc = fmaf(tk[4 * i + 0], ww.x, acc);
        acc = fmaf(tk[4 * i + 1], ww.y, acc);
        acc = fmaf(tk[4 * i + 2], ww.z, acc);
        acc = fmaf(tk[4 * i + 3], ww.w, acc);
    }
    return acc;
}

__global__ __launch_bounds__(NTHR, 1)
void vit_fused_kernel(
    const float* __restrict__ x,        // (B,3,28,28)
    const float* __restrict__ pos_emb,  // (7,7,16)
    const float* __restrict__ WQ1,      // (49,16,32)
    const float* __restrict__ WK1,
    const float* __restrict__ WV1,
    const float* __restrict__ WQ2,      // (49,8,16)
    const float* __restrict__ WK2,
    const float* __restrict__ WV2,
    const float* __restrict__ fc1w,     // (16,392)
    const float* __restrict__ fc1b,     // (16)
    const float* __restrict__ fc2w,     // (10,16)
    const float* __restrict__ fc2b,     // (10)
    float* __restrict__ out,            // (B,10)
    int B)
{
    extern __shared__ float sh[];

    const int tid  = threadIdx.x;
    const int lane = tid & 31;
    const int t    = tid & 15;       // dim index within sample
    const int ls   = tid >> 4;       // sample index within block
    const int shbase = lane & 16;    // lane base of my sample within the warp
    const int b0   = blockIdx.x * GRP;
    const int b    = b0 + ls;

    // ================= Phase 0: load x -> grayscale patches; stage constants =================
    for (int idx = tid; idx < GRP * 784; idx += NTHR) {
        int lsi = idx / 784;
        int pix = idx - lsi * 784;
        int bb = b0 + lsi;
        if (bb < B) {
            const float* xp = x + (size_t)bb * 2352 + pix;
            float g = 0.299f * xp[0] + 0.587f * xp[784] + 0.114f * xp[1568];
            int y  = pix / 28;
            int xx = pix - y * 28;
            int s  = (y >> 2) * 7 + (xx >> 2);
            int q  = (y & 3) * 4 + (xx & 3);
            sh[SM_PB + lsi * 784 + s * 16 + q] = g;
        }
    }
    for (int idx = tid; idx < 784; idx += NTHR) sh[SM_PE + idx] = pos_emb[idx];
    for (int idx = tid; idx < 6272; idx += NTHR) {
        int j = idx / 392, k = idx - j * 392;
        sh[SM_F1W + j * 396 + k] = fc1w[idx];
    }
    if (tid < 160) sh[SM_F2W + tid] = fc2w[tid];
    if (tid < 16)  sh[SM_F1B + tid] = fc1b[tid];
    if (tid < 10)  sh[SM_F2B + tid] = fc2b[tid];
    // (barrier provided by first chunk-load __syncthreads below)

    // ================= Layer 1: projections + attention gram =================
    float S1[16];
#pragma unroll
    for (int e = 0; e < 16; e++) S1[e] = 0.f;

    for (int c0 = 0; c0 < 49; c0 += 7) {
        __syncthreads();
        // stage 7 patches of WQ1/WK1/WV1 (rows padded to 36 floats)
#pragma unroll
        for (int m = 0; m < 3; m++) {
            const float* src = (m == 0) ? WQ1 : ((m == 1) ? WK1 : WV1);
            for (int idx = tid; idx < 7 * 512; idx += NTHR) {
                int j = idx >> 9, rr = idx & 511;
                int d = rr >> 5, i = rr & 31;
                sh[SM_WCH + ((j * 3 + m) * 16 + d) * 36 + i] = src[c0 * 512 + idx];
            }
        }
        __syncthreads();

        for (int s = c0; s < c0 + 7; s++) {
            // tok1[s] -> registers (broadcast smem reads)
            float tk[32];
            const float* pb = &sh[SM_PB + ls * 784 + s * 16];
            const float* pe = &sh[SM_PE + s * 16];
#pragma unroll
            for (int i = 0; i < 4; i++) {
                float4 a = *reinterpret_cast<const float4*>(pb + 4 * i);
                tk[4 * i + 0] = a.x; tk[4 * i + 1] = a.y; tk[4 * i + 2] = a.z; tk[4 * i + 3] = a.w;
                float4 p = *reinterpret_cast<const float4*>(pe + 4 * i);
                tk[16 + 4 * i + 0] = p.x; tk[16 + 4 * i + 1] = p.y;
                tk[16 + 4 * i + 2] = p.z; tk[16 + 4 * i + 3] = p.w;
            }
            const float* wq = &sh[SM_WCH + (((s - c0) * 3 + 0) * 16 + t) * 36];
            const float* wk = &sh[SM_WCH + (((s - c0) * 3 + 1) * 16 + t) * 36];
            const float* wv = &sh[SM_WCH + (((s - c0) * 3 + 2) * 16 + t) * 36];
            float q = dot32_v4(wq, tk) * 0.14285714285714285f;  // fold 1/sqrt(49)
            float k = dot32_v4(wk, tk);
            float v = dot32_v4(wv, tk);
            sh[SM_V1 + ls * 784 + s * 16 + t] = v;
            // S1[d][e] += q[d] * k[e]  via warp shuffle broadcast of k
#pragma unroll
            for (int e = 0; e < 16; e++) {
                float ke = __shfl_sync(0xffffffffu, k, shbase + e, 32);
                S1[e] = fmaf(q, ke, S1[e]);
            }
        }
    }
    __syncwarp();

    // A1[s,d] = sum_e S1[d,e] * V1[s,e]  -> write tok2 into PB
    for (int s = 0; s < 49; s++) {
        const float* vv = &sh[SM_V1 + ls * 784 + s * 16];
        float a = 0.f;
#pragma unroll
        for (int j = 0; j < 4; j++) {
            float4 v4 = *reinterpret_cast<const float4*>(vv + 4 * j);
            a = fmaf(S1[4 * j + 0], v4.x, a);
            a = fmaf(S1[4 * j + 1], v4.y, a);
            a = fmaf(S1[4 * j + 2], v4.z, a);
            a = fmaf(S1[4 * j + 3], v4.w, a);
        }
        sh[SM_PB + ls * 784 + s * 16 + t] = a;
    }
    __syncwarp();

    // softmax over d (16) per row s; rows distributed t, t+16, t+32, (t=0 also 48)
    for (int s = t; s < 49; s += 16) {
        float* row = &sh[SM_PB + ls * 784 + s * 16];
        float m = row[0];
#pragma unroll
        for (int e = 1; e < 16; e++) m = fmaxf(m, row[e]);
        float ex[16], sum = 0.f;
#pragma unroll
        for (int e = 0; e < 16; e++) { ex[e] = __expf(row[e] - m); sum += ex[e]; }
        float inv = 1.f / sum;
#pragma unroll
        for (int e = 0; e < 16; e++) row[e] = ex[e] * inv;
    }
    __syncwarp();

    // ================= Layer 2 =================
    float S2[8];
#pragma unroll
    for (int e = 0; e < 8; e++) S2[e] = 0.f;

    for (int c0 = 0; c0 < 49; c0 += 7) {
        __syncthreads();
#pragma unroll
        for (int m = 0; m < 3; m++) {
            const float* src = (m == 0) ? WQ2 : ((m == 1) ? WK2 : WV2);
            for (int idx = tid; idx < 7 * 128; idx += NTHR) {
                int j = idx >> 7, rr = idx & 127;
                int d = rr >> 4, i = rr & 15;
                sh[SM_WCH + ((j * 3 + m) * 8 + d) * 20 + i] = src[c0 * 128 + idx];
            }
        }
        __syncthreads();

        for (int s = c0; s < c0 + 7; s++) {
            float u[16];
            const float* pb = &sh[SM_PB + ls * 784 + s * 16];
#pragma unroll
            for (int i = 0; i < 4; i++) {
                float4 a = *reinterpret_cast<const float4*>(pb + 4 * i);
                u[4 * i + 0] = a.x; u[4 * i + 1] = a.y; u[4 * i + 2] = a.z; u[4 * i + 3] = a.w;
            }
            float q2 = 0.f, k2 = 0.f;
            if (t < 8) {
                const float* wq = &sh[SM_WCH + (((s - c0) * 3 + 0) * 8 + t) * 20];
                const float* wv = &sh[SM_WCH + (((s - c0) * 3 + 2) * 8 + t) * 20];
                q2 = dot16_v4(wq, u) * 0.14285714285714285f;
                float v2 = dot16_v4(wv, u);
                sh[SM_V2 + ls * 392 + s * 8 + t] = v2;
            } else {
                const float* wk = &sh[SM_WCH + (((s - c0) * 3 + 1) * 8 + (t - 8)) * 20];
                k2 = dot16_v4(wk, u);
            }
#pragma unroll
            for (int e = 0; e < 8; e++) {
                float ke = __shfl_sync(0xffffffffu, k2, shbase + 8 + e, 32);
                S2[e] = fmaf(q2, ke, S2[e]);   // q2==0 for t>=8, harmless
            }
        }
    }
    __syncwarp();

    // A2 -> tok3 (stored in V1 region, stride 8)
    if (t < 8) {
        for (int s = 0; s < 49; s++) {
            const float* vv = &sh[SM_V2 + ls * 392 + s * 8];
            float a = 0.f;
#pragma unroll
            for (int j = 0; j < 2; j++) {
                float4 v4 = *reinterpret_cast<const float4*>(vv + 4 * j);
                a = fmaf(S2[4 * j + 0], v4.x, a);
                a = fmaf(S2[4 * j + 1], v4.y, a);
                a = fmaf(S2[4 * j + 2], v4.z, a);
                a = fmaf(S2[4 * j + 3], v4.w, a);
            }
            sh[SM_V1 + ls * 392 + s * 8 + t] = a;
        }
    }
    __syncwarp();

    for (int s = t; s < 49; s += 16) {
        float* row = &sh[SM_V1 + ls * 392 + s * 8];
        float m = row[0];
#pragma unroll
        for (int e = 1; e < 8; e++) m = fmaxf(m, row[e]);
        float ex[8], sum = 0.f;
#pragma unroll
        for (int e = 0; e < 8; e++) { ex[e] = __expf(row[e] - m); sum += ex[e]; }
        float inv = 1.f / sum;
#pragma unroll
        for (int e = 0; e < 8; e++) row[e] = ex[e] * inv;
    }
    __syncwarp();

    // ================= FC head =================
    {
        float acc = sh[SM_F1B + t];
        const float* fr = &sh[SM_F1W + t * 396];
        const float* t3 = &sh[SM_V1 + ls * 392];
#pragma unroll 7
        for (int kk = 0; kk < 392; kk += 8) {
            float4 a0 = *reinterpret_cast<const float4*>(t3 + kk);
            float4 a1 = *reinterpret_cast<const float4*>(t3 + kk + 4);
            float4 w0 = *reinterpret_cast<const float4*>(fr + kk);
            float4 w1 = *reinterpret_cast<const float4*>(fr + kk + 4);
            acc = fmaf(a0.x, w0.x, acc); acc = fmaf(a0.y, w0.y, acc);
            acc = fmaf(a0.z, w0.z, acc); acc = fmaf(a0.w, w0.w, acc);
            acc = fmaf(a1.x, w1.x, acc); acc = fmaf(a1.y, w1.y, acc);
            acc = fmaf(a1.z, w1.z, acc); acc = fmaf(a1.w, w1.w, acc);
        }
        sh[SM_H + ls * 16 + t] = fmaxf(acc, 0.f);
    }
    __syncwarp();

    {
        float lg = 0.f;
        if (t < 10) {
            const float* w  = &sh[SM_F2W + t * 16];
            const float* hh = &sh[SM_H + ls * 16];
#pragma unroll
            for (int j = 0; j < 16; j++) lg = fmaf(hh[j], w[j], lg);
            lg += sh[SM_F2B + t];
        }
        sh[SM_LG + ls * 16 + t] = lg;
    }
    __syncwarp();

    if (t == 0 && b < B) {
        const float* lrow = &sh[SM_LG + ls * 16];
        float m = lrow[0];
#pragma unroll
        for (int c = 1; c < 10; c++) m = fmaxf(m, lrow[c]);
        float ex[10], sum = 0.f;
#pragma unroll
        for (int c = 0; c < 10; c++) { ex[c] = __expf(lrow[c] - m); sum += ex[c]; }
        float inv = 1.f / sum;
        float* o = out + (size_t)b * 10;
#pragma unroll
        for (int c = 0; c < 10; c++) o[c] = ex[c] * inv;
    }
}

extern "C" void kernel_launch(void* const* d_in, const int* in_sizes, int n_in,
                              void* d_out, int out_size) {
    const float* x   = (const float*)d_in[0];
    const float* pe  = (const float*)d_in[1];
    const float* WQ1 = (const float*)d_in[2];
    const float* WK1 = (const float*)d_in[3];
    const float* WV1 = (const float*)d_in[4];
    const float* WQ2 = (const float*)d_in[5];
    const float* WK2 = (const float*)d_in[6];
    const float* WV2 = (const float*)d_in[7];
    const float* f1w = (const float*)d_in[8];
    const float* f1b = (const float*)d_in[9];
    const float* f2w = (const float*)d_in[10];
    const float* f2b = (const float*)d_in[11];
    float* out = (float*)d_out;

    int B = in_sizes[0] / (3 * 28 * 28);
    int grid = (B + GRP - 1) / GRP;
    size_t smem = (size_t)SM_TOT * sizeof(float);

    cudaFuncSetAttribute(vit_fused_kernel,
                         cudaFuncAttributeMaxDynamicSharedMemorySize, (int)smem);
    vit_fused_kernel<<<grid, NTHR, smem>>>(x, pe, WQ1, WK1, WV1, WQ2, WK2, WV2,
                                           f1w, f1b, f2w, f2b, out, B);
}

// round 4
// speedup vs baseline: 1.7449x; 1.7449x over previous
#include <cuda_runtime.h>
#include <math.h>

// ViT fused, 256 thr = 16 samples x 16 threads. 104.5KB smem -> 2 CTAs/SM.
// One 784-float buffer per sample: patches -> V1 -> tok2 -> V2 -> tok3 (in place).

#define GRP  16
#define NTHR 256

static constexpr int SM_PB  = 0;                  // 16*784
static constexpr int SM_PE  = GRP * 784;          // 784
static constexpr int SM_WCH = SM_PE + 784;        // 12096 (L1 chunk / L2 chunk / F1W 16*396=6336)
static constexpr int SM_F2W = SM_WCH + 12096;     // 160
static constexpr int SM_F1B = SM_F2W + 160;       // 16
static constexpr int SM_F2B = SM_F1B + 16;        // 16
static constexpr int SM_H   = SM_F2B + 16;        // 256
static constexpr int SM_LG  = SM_H + 256;         // 256
static constexpr int SM_TOT = SM_LG + 256;        // 26128 floats = 104512 B

__device__ __forceinline__ float dot32(const float* __restrict__ w, const float* tk) {
    float acc = 0.f;
#pragma unroll
    for (int i = 0; i < 8; i++) {
        float4 ww = *reinterpret_cast<const float4*>(w + 4 * i);
        acc = fmaf(tk[4 * i + 0], ww.x, acc);
        acc = fmaf(tk[4 * i + 1], ww.y, acc);
        acc = fmaf(tk[4 * i + 2], ww.z, acc);
        acc = fmaf(tk[4 * i + 3], ww.w, acc);
    }
    return acc;
}

__device__ __forceinline__ float dot16(const float* __restrict__ w, const float* tk) {
    float acc = 0.f;
#pragma unroll
    for (int i = 0; i < 4; i++) {
        float4 ww = *reinterpret_cast<const float4*>(w + 4 * i);
        acc = fmaf(tk[4 * i + 0], ww.x, acc);
        acc = fmaf(tk[4 * i + 1], ww.y, acc);
        acc = fmaf(tk[4 * i + 2], ww.z, acc);
        acc = fmaf(tk[4 * i + 3], ww.w, acc);
    }
    return acc;
}

__global__ __launch_bounds__(NTHR, 2)
void vit_fused_kernel(
    const float* __restrict__ x, const float* __restrict__ pos_emb,
    const float* __restrict__ WQ1, const float* __restrict__ WK1, const float* __restrict__ WV1,
    const float* __restrict__ WQ2, const float* __restrict__ WK2, const float* __restrict__ WV2,
    const float* __restrict__ fc1w, const float* __restrict__ fc1b,
    const float* __restrict__ fc2w, const float* __restrict__ fc2b,
    float* __restrict__ out, int B)
{
    extern __shared__ float sh[];
    const int tid  = threadIdx.x;
    const int lane = tid & 31;
    const int t    = tid & 15;
    const int ls   = tid >> 4;
    const int shbase = lane & 16;
    const int b0   = blockIdx.x * GRP;
    const int b    = b0 + ls;

    // ---------- phase 0 ----------
    for (int idx = tid; idx < GRP * 784; idx += NTHR) {
        int lsi = idx / 784, pix = idx - lsi * 784;
        int bb = b0 + lsi;
        float g = 0.f;
        if (bb < B) {
            const float* xp = x + (size_t)bb * 2352 + pix;
            g = 0.299f * xp[0] + 0.587f * xp[784] + 0.114f * xp[1568];
        }
        int y = pix / 28, xx = pix - y * 28;
        sh[SM_PB + lsi * 784 + ((y >> 2) * 7 + (xx >> 2)) * 16 + (y & 3) * 4 + (xx & 3)] = g;
    }
    for (int idx = tid; idx < 784; idx += NTHR) sh[SM_PE + idx] = pos_emb[idx];
    if (tid < 160) sh[SM_F2W + tid] = fc2w[tid];
    if (tid < 16)  sh[SM_F1B + tid] = fc1b[tid];
    if (tid < 10)  sh[SM_F2B + tid] = fc2b[tid];

    // ---------- layer 1: projections + gram ----------
    float S1[16];
#pragma unroll
    for (int e = 0; e < 16; e++) S1[e] = 0.f;

    for (int c0 = 0; c0 < 49; c0 += 7) {
        __syncthreads();
#pragma unroll
        for (int m = 0; m < 3; m++) {
            const float* src = (m == 0) ? WQ1 : (m == 1) ? WK1 : WV1;
            for (int idx = tid; idx < 7 * 512; idx += NTHR) {
                int j = idx >> 9, rr = idx & 511, d = rr >> 5, i = rr & 31;
                sh[SM_WCH + ((j * 3 + m) * 16 + d) * 36 + i] = src[c0 * 512 + idx];
            }
        }
        __syncthreads();

        for (int s = c0; s < c0 + 7; s++) {
            float tk[32];
            const float* pb = &sh[SM_PB + ls * 784 + s * 16];
            const float* pe = &sh[SM_PE + s * 16];
#pragma unroll
            for (int i = 0; i < 4; i++) {
                float4 a = *reinterpret_cast<const float4*>(pb + 4 * i);
                tk[4*i+0] = a.x; tk[4*i+1] = a.y; tk[4*i+2] = a.z; tk[4*i+3] = a.w;
                float4 p = *reinterpret_cast<const float4*>(pe + 4 * i);
                tk[16+4*i+0] = p.x; tk[16+4*i+1] = p.y; tk[16+4*i+2] = p.z; tk[16+4*i+3] = p.w;
            }
            const float* wq = &sh[SM_WCH + (((s - c0) * 3 + 0) * 16 + t) * 36];
            const float* wk = &sh[SM_WCH + (((s - c0) * 3 + 1) * 16 + t) * 36];
            const float* wv = &sh[SM_WCH + (((s - c0) * 3 + 2) * 16 + t) * 36];
            float q = dot32(wq, tk) * 0.14285714285714285f;
            float k = dot32(wk, tk);
            float v = dot32(wv, tk);
            __syncwarp();
            sh[SM_PB + ls * 784 + s * 16 + t] = v;   // V over patches (reads done)
#pragma unroll
            for (int e = 0; e < 16; e++) {
                float ke = __shfl_sync(0xffffffffu, k, shbase + e, 32);
                S1[e] = fmaf(q, ke, S1[e]);
            }
        }
    }
    __syncwarp();

    // A1: tok2[s] over V[s], in place
    for (int s = 0; s < 49; s++) {
        const float* vv = &sh[SM_PB + ls * 784 + s * 16];
        float4 v0 = *reinterpret_cast<const float4*>(vv);
        float4 v1 = *reinterpret_cast<const float4*>(vv + 4);
        float4 v2 = *reinterpret_cast<const float4*>(vv + 8);
        float4 v3 = *reinterpret_cast<const float4*>(vv + 12);
        float a = 0.f;
        a = fmaf(S1[0],  v0.x, a); a = fmaf(S1[1],  v0.y, a);
        a = fmaf(S1[2],  v0.z, a); a = fmaf(S1[3],  v0.w, a);
        a = fmaf(S1[4],  v1.x, a); a = fmaf(S1[5],  v1.y, a);
        a = fmaf(S1[6],  v1.z, a); a = fmaf(S1[7],  v1.w, a);
        a = fmaf(S1[8],  v2.x, a); a = fmaf(S1[9],  v2.y, a);
        a = fmaf(S1[10], v2.z, a); a = fmaf(S1[11], v2.w, a);
        a = fmaf(S1[12], v3.x, a); a = fmaf(S1[13], v3.y, a);
        a = fmaf(S1[14], v3.z, a); a = fmaf(S1[15], v3.w, a);
        __syncwarp();
        sh[SM_PB + ls * 784 + s * 16 + t] = a;
    }
    __syncwarp();

    // softmax1 (16-wide rows; rows distributed across the 16 threads)
    for (int s = t; s < 49; s += 16) {
        float* row = &sh[SM_PB + ls * 784 + s * 16];
        float m = row[0];
#pragma unroll
        for (int e = 1; e < 16; e++) m = fmaxf(m, row[e]);
        float ex[16], sum = 0.f;
#pragma unroll
        for (int e = 0; e < 16; e++) { ex[e] = __expf(row[e] - m); sum += ex[e]; }
        float inv = 1.f / sum;
#pragma unroll
        for (int e = 0; e < 16; e++) row[e] = ex[e] * inv;
    }
    __syncwarp();

    // ---------- layer 2 ----------
    float S2[8];
#pragma unroll
    for (int e = 0; e < 8; e++) S2[e] = 0.f;

    for (int c0 = 0; c0 < 49; c0 += 7) {
        __syncthreads();
#pragma unroll
        for (int m = 0; m < 3; m++) {
            const float* src = (m == 0) ? WQ2 : (m == 1) ? WK2 : WV2;
            for (int idx = tid; idx < 7 * 128; idx += NTHR) {
                int j = idx >> 7, rr = idx & 127, d = rr >> 4, i = rr & 15;
                sh[SM_WCH + ((j * 3 + m) * 8 + d) * 20 + i] = src[c0 * 128 + idx];
            }
        }
        __syncthreads();

        for (int s = c0; s < c0 + 7; s++) {
            float u[16];
            const float* pb = &sh[SM_PB + ls * 784 + s * 16];
#pragma unroll
            for (int i = 0; i < 4; i++) {
                float4 a = *reinterpret_cast<const float4*>(pb + 4 * i);
                u[4*i+0] = a.x; u[4*i+1] = a.y; u[4*i+2] = a.z; u[4*i+3] = a.w;
            }
            float q2 = 0.f, k2 = 0.f, v2 = 0.f;
            if (t < 8) {
                const float* wq = &sh[SM_WCH + (((s - c0) * 3 + 0) * 8 + t) * 20];
                const float* wv = &sh[SM_WCH + (((s - c0) * 3 + 2) * 8 + t) * 20];
                q2 = dot16(wq, u) * 0.14285714285714285f;
                v2 = dot16(wv, u);
            } else {
                const float* wk = &sh[SM_WCH + (((s - c0) * 3 + 1) * 8 + (t - 8)) * 20];
                k2 = dot16(wk, u);
            }
            __syncwarp();
            if (t < 8) sh[SM_PB + ls * 784 + s * 16 + t] = v2;   // V2 over tok2[0:8]
#pragma unroll
            for (int e = 0; e < 8; e++) {
                float ke = __shfl_sync(0xffffffffu, k2, shbase + 8 + e, 32);
                S2[e] = fmaf(q2, ke, S2[e]);  // q2==0 for t>=8
            }
        }
    }
    __syncwarp();

    // A2: tok3[s] over V2[s], in place (threads t<8)
    for (int s = 0; s < 49; s++) {
        float a = 0.f;
        if (t < 8) {
            const float* vv = &sh[SM_PB + ls * 784 + s * 16];
            float4 v0 = *reinterpret_cast<const float4*>(vv);
            float4 v1 = *reinterpret_cast<const float4*>(vv + 4);
            a = fmaf(S2[0], v0.x, a); a = fmaf(S2[1], v0.y, a);
            a = fmaf(S2[2], v0.z, a); a = fmaf(S2[3], v0.w, a);
            a = fmaf(S2[4], v1.x, a); a = fmaf(S2[5], v1.y, a);
            a = fmaf(S2[6], v1.z, a); a = fmaf(S2[7], v1.w, a);
        }
        __syncwarp();
        if (t < 8) sh[SM_PB + ls * 784 + s * 16 + t] = a;
    }
    __syncwarp();

    // softmax2 (8-wide rows at stride 16)
    for (int s = t; s < 49; s += 16) {
        float* row = &sh[SM_PB + ls * 784 + s * 16];
        float m = row[0];
#pragma unroll
        for (int e = 1; e < 8; e++) m = fmaxf(m, row[e]);
        float ex[8], sum = 0.f;
#pragma unroll
        for (int e = 0; e < 8; e++) { ex[e] = __expf(row[e] - m); sum += ex[e]; }
        float inv = 1.f / sum;
#pragma unroll
        for (int e = 0; e < 8; e++) row[e] = ex[e] * inv;
    }

    // ---------- stage fc1w into dead WCH, then FC head ----------
    __syncthreads();
    for (int idx = tid; idx < 6272; idx += NTHR) {
        int j = idx / 392, k = idx - j * 392;
        sh[SM_WCH + j * 396 + k] = fc1w[idx];
    }
    __syncthreads();

    {
        float acc = sh[SM_F1B + t];
        const float* fr = &sh[SM_WCH + t * 396];
        const float* t3 = &sh[SM_PB + ls * 784];
#pragma unroll 7
        for (int s = 0; s < 49; s++) {
            float4 a0 = *reinterpret_cast<const float4*>(t3 + s * 16);
            float4 a1 = *reinterpret_cast<const float4*>(t3 + s * 16 + 4);
            float4 w0 = *reinterpret_cast<const float4*>(fr + s * 8);
            float4 w1 = *reinterpret_cast<const float4*>(fr + s * 8 + 4);
            acc = fmaf(a0.x, w0.x, acc); acc = fmaf(a0.y, w0.y, acc);
            acc = fmaf(a0.z, w0.z, acc); acc = fmaf(a0.w, w0.w, acc);
            acc = fmaf(a1.x, w1.x, acc); acc = fmaf(a1.y, w1.y, acc);
            acc = fmaf(a1.z, w1.z, acc); acc = fmaf(a1.w, w1.w, acc);
        }
        sh[SM_H + ls * 16 + t] = fmaxf(acc, 0.f);
    }
    __syncwarp();

    {
        float lg = 0.f;
        if (t < 10) {
            const float* w  = &sh[SM_F2W + t * 16];
            const float* hh = &sh[SM_H + ls * 16];
#pragma unroll
            for (int j = 0; j < 16; j++) lg = fmaf(hh[j], w[j], lg);
            lg += sh[SM_F2B + t];
        }
        sh[SM_LG + ls * 16 + t] = lg;
    }
    __syncwarp();

    if (t == 0 && b < B) {
        const float* lrow = &sh[SM_LG + ls * 16];
        float m = lrow[0];
#pragma unroll
        for (int c = 1; c < 10; c++) m = fmaxf(m, lrow[c]);
        float ex[10], sum = 0.f;
#pragma unroll
        for (int c = 0; c < 10; c++) { ex[c] = __expf(lrow[c] - m); sum += ex[c]; }
        float inv = 1.f / sum;
        float* o = out + (size_t)b * 10;
#pragma unroll
        for (int c = 0; c < 10; c++) o[c] = ex[c] * inv;
    }
}

extern "C" void kernel_launch(void* const* d_in, const int* in_sizes, int n_in,
                              void* d_out, int out_size) {
    const float* x   = (const float*)d_in[0];
    const float* pe  = (const float*)d_in[1];
    const float* WQ1 = (const float*)d_in[2];
    const float* WK1 = (const float*)d_in[3];
    const float* WV1 = (const float*)d_in[4];
    const float* WQ2 = (const float*)d_in[5];
    const float* WK2 = (const float*)d_in[6];
    const float* WV2 = (const float*)d_in[7];
    const float* f1w = (const float*)d_in[8];
    const float* f1b = (const float*)d_in[9];
    const float* f2w = (const float*)d_in[10];
    const float* f2b = (const float*)d_in[11];
    float* out = (float*)d_out;

    int B = in_sizes[0] / (3 * 28 * 28);
    int grid = (B + GRP - 1) / GRP;
    size_t smem = (size_t)SM_TOT * sizeof(float);

    cudaFuncSetAttribute(vit_fused_kernel,
                         cudaFuncAttributeMaxDynamicSharedMemorySize, (int)smem);
    vit_fused_kernel<<<grid, NTHR, smem>>>(x, pe, WQ1, WK1, WV1, WQ2, WK2, WV2,
                                           f1w, f1b, f2w, f2b, out, B);
}

// round 5
// speedup vs baseline: 2.0368x; 1.1673x over previous
#include <cuda_runtime.h>
#include <math.h>

// ViT fused. 256 thr = 16 samples x 16 threads. 68.3KB smem, <=84 regs -> 3 CTAs/SM.
// In-place per-sample buffer: patches -> V1 -> tok2 -> V2 -> tok3.
// V writes deferred via pending regs (hazard-free, no syncwarp in hot loops).

#define GRP  16
#define NTHR 256

static constexpr int SM_PB  = 0;        // 16*784 = 12544
static constexpr int SM_PE  = 12544;    // 784
static constexpr int SM_WCH = 13328;    // 3456 (L1 chunk 2*3*16*36=3456 / L2 chunk 7*3*8*20=3360 / fc1w half 16*200=3200)
static constexpr int SM_F2W = 16784;    // 160
static constexpr int SM_F1B = 16944;    // 16
static constexpr int SM_F2B = 16960;    // 16
static constexpr int SM_H   = 16976;    // 256
static constexpr int SM_LG  = 17232;    // 256
static constexpr int SM_TOT = 17488;    // 69952 bytes

__global__ __launch_bounds__(NTHR, 3)
void vit_fused_kernel(
    const float* __restrict__ x, const float* __restrict__ pos_emb,
    const float* __restrict__ WQ1, const float* __restrict__ WK1, const float* __restrict__ WV1,
    const float* __restrict__ WQ2, const float* __restrict__ WK2, const float* __restrict__ WV2,
    const float* __restrict__ fc1w, const float* __restrict__ fc1b,
    const float* __restrict__ fc2w, const float* __restrict__ fc2b,
    float* __restrict__ out, int B)
{
    extern __shared__ float sh[];
    const int tid  = threadIdx.x;
    const int lane = tid & 31;
    const int t    = tid & 15;
    const int ls   = tid >> 4;
    const int shbase = lane & 16;
    const int b0   = blockIdx.x * GRP;
    const int b    = b0 + ls;
    const float INV7 = 0.14285714285714285f;
    float* myrow = &sh[SM_PB + ls * 784];

    // ---------------- phase 0: patchify + constants ----------------
    for (int idx = tid; idx < GRP * 784; idx += NTHR) {
        int lsi = idx / 784, pix = idx - lsi * 784;
        int bb = b0 + lsi;
        float g = 0.f;
        if (bb < B) {
            const float* xp = x + (size_t)bb * 2352 + pix;
            g = 0.299f * xp[0] + 0.587f * xp[784] + 0.114f * xp[1568];
        }
        int y = pix / 28, xx = pix - y * 28;
        sh[SM_PB + lsi * 784 + ((y >> 2) * 7 + (xx >> 2)) * 16 + (y & 3) * 4 + (xx & 3)] = g;
    }
    for (int idx = tid; idx < 784; idx += NTHR) sh[SM_PE + idx] = pos_emb[idx];
    if (tid < 160) sh[SM_F2W + tid] = fc2w[tid];
    if (tid < 16)  sh[SM_F1B + tid] = fc1b[tid];
    if (tid < 10)  sh[SM_F2B + tid] = fc2b[tid];

    // ---------------- layer 1: projections + gram (chunk = 2 patches) ----------------
    float S1[16];
#pragma unroll
    for (int e = 0; e < 16; e++) S1[e] = 0.f;
    float vpend0 = 0.f, vpend1 = 0.f;

#pragma unroll 1
    for (int c0 = 0; c0 < 49; c0 += 2) {
        const int np = (c0 < 48) ? 2 : 1;
        __syncthreads();
        // deferred V writes for previous chunk (ordered by the barrier above)
        if (c0 > 0) {
            myrow[(c0 - 2) * 16 + t] = vpend0;
            myrow[(c0 - 1) * 16 + t] = vpend1;
        }
        // stage weights: rows padded to 36 floats
#pragma unroll
        for (int m = 0; m < 3; m++) {
            const float* src = (m == 0) ? WQ1 : (m == 1) ? WK1 : WV1;
            for (int idx = tid; idx < np * 128; idx += NTHR) {
                int j = idx >> 7, r = idx & 127, d = r >> 3, i4 = r & 7;
                *reinterpret_cast<float4*>(&sh[SM_WCH + ((j * 3 + m) * 16 + d) * 36 + i4 * 4]) =
                    *reinterpret_cast<const float4*>(&src[(c0 + j) * 512 + d * 32 + i4 * 4]);
            }
        }
        __syncthreads();

#pragma unroll
        for (int j = 0; j < 2; j++) {
            if (j < np) {
                const int s = c0 + j;
                const float* wq = &sh[SM_WCH + ((j * 3 + 0) * 16 + t) * 36];
                const float* wk = &sh[SM_WCH + ((j * 3 + 1) * 16 + t) * 36];
                const float* wv = &sh[SM_WCH + ((j * 3 + 2) * 16 + t) * 36];
                float q = 0.f, k = 0.f, v = 0.f;
                // PE part (weight cols 16..31)
                const float4* pe4 = reinterpret_cast<const float4*>(&sh[SM_PE + s * 16]);
#pragma unroll
                for (int i = 0; i < 4; i++) {
                    float4 p  = pe4[i];
                    float4 aq = *reinterpret_cast<const float4*>(wq + 16 + 4 * i);
                    float4 ak = *reinterpret_cast<const float4*>(wk + 16 + 4 * i);
                    float4 av = *reinterpret_cast<const float4*>(wv + 16 + 4 * i);
                    q = fmaf(aq.x, p.x, q); q = fmaf(aq.y, p.y, q);
                    q = fmaf(aq.z, p.z, q); q = fmaf(aq.w, p.w, q);
                    k = fmaf(ak.x, p.x, k); k = fmaf(ak.y, p.y, k);
                    k = fmaf(ak.z, p.z, k); k = fmaf(ak.w, p.w, k);
                    v = fmaf(av.x, p.x, v); v = fmaf(av.y, p.y, v);
                    v = fmaf(av.z, p.z, v); v = fmaf(av.w, p.w, v);
                }
                // patch part (weight cols 0..15)
                const float4* pr = reinterpret_cast<const float4*>(&myrow[s * 16]);
#pragma unroll
                for (int i = 0; i < 4; i++) {
                    float4 a  = pr[i];
                    float4 aq = *reinterpret_cast<const float4*>(wq + 4 * i);
                    float4 ak = *reinterpret_cast<const float4*>(wk + 4 * i);
                    float4 av = *reinterpret_cast<const float4*>(wv + 4 * i);
                    q = fmaf(aq.x, a.x, q); q = fmaf(aq.y, a.y, q);
                    q = fmaf(aq.z, a.z, q); q = fmaf(aq.w, a.w, q);
                    k = fmaf(ak.x, a.x, k); k = fmaf(ak.y, a.y, k);
                    k = fmaf(ak.z, a.z, k); k = fmaf(ak.w, a.w, k);
                    v = fmaf(av.x, a.x, v); v = fmaf(av.y, a.y, v);
                    v = fmaf(av.z, a.z, v); v = fmaf(av.w, a.w, v);
                }
                q *= INV7;
                if (j == 0) vpend0 = v; else vpend1 = v;
#pragma unroll
                for (int e = 0; e < 16; e++) {
                    float ke = __shfl_sync(0xffffffffu, k, shbase + e, 32);
                    S1[e] = fmaf(q, ke, S1[e]);
                }
            }
        }
    }
    // flush last pending V (row 48): cross-lane reads of row 48 finished before here
    __syncwarp();
    myrow[48 * 16 + t] = vpend0;
    __syncwarp();

    // ---------------- A1: tok2[s,d] = sum_e S1[d,e] V[s,e]  (in place) ----------------
#pragma unroll 1
    for (int s = 0; s < 49; s++) {
        const float4* vr = reinterpret_cast<const float4*>(&myrow[s * 16]);
        float4 v0 = vr[0], v1 = vr[1], v2 = vr[2], v3 = vr[3];
        float a0 = 0.f, a1 = 0.f;
        a0 = fmaf(S1[0],  v0.x, a0); a1 = fmaf(S1[1],  v0.y, a1);
        a0 = fmaf(S1[2],  v0.z, a0); a1 = fmaf(S1[3],  v0.w, a1);
        a0 = fmaf(S1[4],  v1.x, a0); a1 = fmaf(S1[5],  v1.y, a1);
        a0 = fmaf(S1[6],  v1.z, a0); a1 = fmaf(S1[7],  v1.w, a1);
        a0 = fmaf(S1[8],  v2.x, a0); a1 = fmaf(S1[9],  v2.y, a1);
        a0 = fmaf(S1[10], v2.z, a0); a1 = fmaf(S1[11], v2.w, a1);
        a0 = fmaf(S1[12], v3.x, a0); a1 = fmaf(S1[13], v3.y, a1);
        a0 = fmaf(S1[14], v3.z, a0); a1 = fmaf(S1[15], v3.w, a1);
        __syncwarp();
        myrow[s * 16 + t] = a0 + a1;
    }
    __syncwarp();

    // ---------------- softmax1 over 16 dims ----------------
#pragma unroll 1
    for (int s = t; s < 49; s += 16) {
        float4* row = reinterpret_cast<float4*>(&myrow[s * 16]);
        float4 r0 = row[0], r1 = row[1], r2 = row[2], r3 = row[3];
        float m = fmaxf(fmaxf(fmaxf(r0.x, r0.y), fmaxf(r0.z, r0.w)),
                        fmaxf(fmaxf(r1.x, r1.y), fmaxf(r1.z, r1.w)));
        m = fmaxf(m, fmaxf(fmaxf(fmaxf(r2.x, r2.y), fmaxf(r2.z, r2.w)),
                           fmaxf(fmaxf(r3.x, r3.y), fmaxf(r3.z, r3.w))));
        r0.x = __expf(r0.x - m); r0.y = __expf(r0.y - m); r0.z = __expf(r0.z - m); r0.w = __expf(r0.w - m);
        r1.x = __expf(r1.x - m); r1.y = __expf(r1.y - m); r1.z = __expf(r1.z - m); r1.w = __expf(r1.w - m);
        r2.x = __expf(r2.x - m); r2.y = __expf(r2.y - m); r2.z = __expf(r2.z - m); r2.w = __expf(r2.w - m);
        r3.x = __expf(r3.x - m); r3.y = __expf(r3.y - m); r3.z = __expf(r3.z - m); r3.w = __expf(r3.w - m);
        float sum = (r0.x + r0.y + r0.z + r0.w) + (r1.x + r1.y + r1.z + r1.w)
                  + (r2.x + r2.y + r2.z + r2.w) + (r3.x + r3.y + r3.z + r3.w);
        float inv = 1.f / sum;
        r0.x *= inv; r0.y *= inv; r0.z *= inv; r0.w *= inv;
        r1.x *= inv; r1.y *= inv; r1.z *= inv; r1.w *= inv;
        r2.x *= inv; r2.y *= inv; r2.z *= inv; r2.w *= inv;
        r3.x *= inv; r3.y *= inv; r3.z *= inv; r3.w *= inv;
        row[0] = r0; row[1] = r1; row[2] = r2; row[3] = r3;
    }

    // ---------------- layer 2: projections + gram (chunk = 7 patches) ----------------
    float S2[8];
#pragma unroll
    for (int e = 0; e < 8; e++) S2[e] = 0.f;
    float v2p[7];
#pragma unroll
    for (int j = 0; j < 7; j++) v2p[j] = 0.f;

#pragma unroll 1
    for (int c0 = 0; c0 < 49; c0 += 7) {
        __syncthreads();
        if (c0 > 0 && t < 8) {
#pragma unroll
            for (int j = 0; j < 7; j++) myrow[(c0 - 7 + j) * 16 + t] = v2p[j];
        }
#pragma unroll
        for (int m = 0; m < 3; m++) {
            const float* src = (m == 0) ? WQ2 : (m == 1) ? WK2 : WV2;
            for (int idx = tid; idx < 7 * 32; idx += NTHR) {
                int j = idx >> 5, r = idx & 31, d = r >> 2, i4 = r & 3;
                *reinterpret_cast<float4*>(&sh[SM_WCH + ((j * 3 + m) * 8 + d) * 20 + i4 * 4]) =
                    *reinterpret_cast<const float4*>(&src[(c0 + j) * 128 + d * 16 + i4 * 4]);
            }
        }
        __syncthreads();

#pragma unroll 1
        for (int j = 0; j < 7; j++) {
            const int s = c0 + j;
            const float4* ur = reinterpret_cast<const float4*>(&myrow[s * 16]);
            float4 u0 = ur[0], u1 = ur[1], u2 = ur[2], u3 = ur[3];
            float k2 = 0.f, q2 = 0.f;
            if (t < 8) {
                const float* wq = &sh[SM_WCH + ((j * 3 + 0) * 8 + t) * 20];
                const float* wv = &sh[SM_WCH + ((j * 3 + 2) * 8 + t) * 20];
                float v2 = 0.f;
                float4 wa, wb;
                wa = *reinterpret_cast<const float4*>(wq + 0);
                wb = *reinterpret_cast<const float4*>(wv + 0);
                q2 = fmaf(wa.x, u0.x, q2); q2 = fmaf(wa.y, u0.y, q2);
                q2 = fmaf(wa.z, u0.z, q2); q2 = fmaf(wa.w, u0.w, q2);
                v2 = fmaf(wb.x, u0.x, v2); v2 = fmaf(wb.y, u0.y, v2);
                v2 = fmaf(wb.z, u0.z, v2); v2 = fmaf(wb.w, u0.w, v2);
                wa = *reinterpret_cast<const float4*>(wq + 4);
                wb = *reinterpret_cast<const float4*>(wv + 4);
                q2 = fmaf(wa.x, u1.x, q2); q2 = fmaf(wa.y, u1.y, q2);
                q2 = fmaf(wa.z, u1.z, q2); q2 = fmaf(wa.w, u1.w, q2);
                v2 = fmaf(wb.x, u1.x, v2); v2 = fmaf(wb.y, u1.y, v2);
                v2 = fmaf(wb.z, u1.z, v2); v2 = fmaf(wb.w, u1.w, v2);
                wa = *reinterpret_cast<const float4*>(wq + 8);
                wb = *reinterpret_cast<const float4*>(wv + 8);
                q2 = fmaf(wa.x, u2.x, q2); q2 = fmaf(wa.y, u2.y, q2);
                q2 = fmaf(wa.z, u2.z, q2); q2 = fmaf(wa.w, u2.w, q2);
                v2 = fmaf(wb.x, u2.x, v2); v2 = fmaf(wb.y, u2.y, v2);
                v2 = fmaf(wb.z, u2.z, v2); v2 = fmaf(wb.w, u2.w, v2);
                wa = *reinterpret_cast<const float4*>(wq + 12);
                wb = *reinterpret_cast<const float4*>(wv + 12);
                q2 = fmaf(wa.x, u3.x, q2); q2 = fmaf(wa.y, u3.y, q2);
                q2 = fmaf(wa.z, u3.z, q2); q2 = fmaf(wa.w, u3.w, q2);
                v2 = fmaf(wb.x, u3.x, v2); v2 = fmaf(wb.y, u3.y, v2);
                v2 = fmaf(wb.z, u3.z, v2); v2 = fmaf(wb.w, u3.w, v2);
                q2 *= INV7;
                v2p[j] = v2;
            } else {
                const float* wk = &sh[SM_WCH + ((j * 3 + 1) * 8 + (t - 8)) * 20];
                float4 wa;
                wa = *reinterpret_cast<const float4*>(wk + 0);
                k2 = fmaf(wa.x, u0.x, k2); k2 = fmaf(wa.y, u0.y, k2);
                k2 = fmaf(wa.z, u0.z, k2); k2 = fmaf(wa.w, u0.w, k2);
                wa = *reinterpret_cast<const float4*>(wk + 4);
                k2 = fmaf(wa.x, u1.x, k2); k2 = fmaf(wa.y, u1.y, k2);
                k2 = fmaf(wa.z, u1.z, k2); k2 = fmaf(wa.w, u1.w, k2);
                wa = *reinterpret_cast<const float4*>(wk + 8);
                k2 = fmaf(wa.x, u2.x, k2); k2 = fmaf(wa.y, u2.y, k2);
                k2 = fmaf(wa.z, u2.z, k2); k2 = fmaf(wa.w, u2.w, k2);
                wa = *reinterpret_cast<const float4*>(wk + 12);
                k2 = fmaf(wa.x, u3.x, k2); k2 = fmaf(wa.y, u3.y, k2);
                k2 = fmaf(wa.z, u3.z, k2); k2 = fmaf(wa.w, u3.w, k2);
            }
#pragma unroll
            for (int e = 0; e < 8; e++) {
                float ke = __shfl_sync(0xffffffffu, k2, shbase + 8 + e, 32);
                S2[e] = fmaf(q2, ke, S2[e]);  // q2==0 for t>=8
            }
        }
    }
    // flush pending V2 (rows 42..48)
    __syncwarp();
    if (t < 8) {
#pragma unroll
        for (int j = 0; j < 7; j++) myrow[(42 + j) * 16 + t] = v2p[j];
    }
    __syncwarp();

    // ---------------- A2: tok3[s,d] (in place, t<8) ----------------
#pragma unroll 1
    for (int s = 0; s < 49; s++) {
        float a = 0.f;
        if (t < 8) {
            const float4* vr = reinterpret_cast<const float4*>(&myrow[s * 16]);
            float4 v0 = vr[0], v1 = vr[1];
            a = fmaf(S2[0], v0.x, a); a = fmaf(S2[1], v0.y, a);
            a = fmaf(S2[2], v0.z, a); a = fmaf(S2[3], v0.w, a);
            a = fmaf(S2[4], v1.x, a); a = fmaf(S2[5], v1.y, a);
            a = fmaf(S2[6], v1.z, a); a = fmaf(S2[7], v1.w, a);
        }
        __syncwarp();
        if (t < 8) myrow[s * 16 + t] = a;
    }
    __syncwarp();

    // ---------------- softmax2 over 8 dims ----------------
#pragma unroll 1
    for (int s = t; s < 49; s += 16) {
        float4* row = reinterpret_cast<float4*>(&myrow[s * 16]);
        float4 r0 = row[0], r1 = row[1];
        float m = fmaxf(fmaxf(fmaxf(r0.x, r0.y), fmaxf(r0.z, r0.w)),
                        fmaxf(fmaxf(r1.x, r1.y), fmaxf(r1.z, r1.w)));
        r0.x = __expf(r0.x - m); r0.y = __expf(r0.y - m); r0.z = __expf(r0.z - m); r0.w = __expf(r0.w - m);
        r1.x = __expf(r1.x - m); r1.y = __expf(r1.y - m); r1.z = __expf(r1.z - m); r1.w = __expf(r1.w - m);
        float sum = (r0.x + r0.y + r0.z + r0.w) + (r1.x + r1.y + r1.z + r1.w);
        float inv = 1.f / sum;
        r0.x *= inv; r0.y *= inv; r0.z *= inv; r0.w *= inv;
        r1.x *= inv; r1.y *= inv; r1.z *= inv; r1.w *= inv;
        row[0] = r0; row[1] = r1;
    }

    // ---------------- FC head (fc1w staged in two K-halves) ----------------
    float acc = sh[SM_F1B + t];
    // half 0: s in [0,24), weight cols [0,192)
    __syncthreads();
    for (int idx = tid; idx < 768; idx += NTHR) {
        int j = idx / 48, c4 = idx - j * 48;
        *reinterpret_cast<float4*>(&sh[SM_WCH + j * 200 + c4 * 4]) =
            *reinterpret_cast<const float4*>(&fc1w[j * 392 + c4 * 4]);
    }
    __syncthreads();
#pragma unroll 1
    for (int s = 0; s < 24; s++) {
        float4 a0 = *reinterpret_cast<const float4*>(&myrow[s * 16]);
        float4 a1 = *reinterpret_cast<const float4*>(&myrow[s * 16 + 4]);
        float4 w0 = *reinterpret_cast<const float4*>(&sh[SM_WCH + t * 200 + s * 8]);
        float4 w1 = *reinterpret_cast<const float4*>(&sh[SM_WCH + t * 200 + s * 8 + 4]);
        acc = fmaf(a0.x, w0.x, acc); acc = fmaf(a0.y, w0.y, acc);
        acc = fmaf(a0.z, w0.z, acc); acc = fmaf(a0.w, w0.w, acc);
        acc = fmaf(a1.x, w1.x, acc); acc = fmaf(a1.y, w1.y, acc);
        acc = fmaf(a1.z, w1.z, acc); acc = fmaf(a1.w, w1.w, acc);
    }
    // half 1: s in [24,49), weight cols [192,392)
    __syncthreads();
    for (int idx = tid; idx < 800; idx += NTHR) {
        int j = idx / 50, c4 = idx - j * 50;
        *reinterpret_cast<float4*>(&sh[SM_WCH + j * 200 + c4 * 4]) =
            *reinterpret_cast<const float4*>(&fc1w[j * 392 + 192 + c4 * 4]);
    }
    __syncthreads();
#pragma unroll 1
    for (int s = 24; s < 49; s++) {
        float4 a0 = *reinterpret_cast<const float4*>(&myrow[s * 16]);
        float4 a1 = *reinterpret_cast<const float4*>(&myrow[s * 16 + 4]);
        float4 w0 = *reinterpret_cast<const float4*>(&sh[SM_WCH + t * 200 + (s - 24) * 8]);
        float4 w1 = *reinterpret_cast<const float4*>(&sh[SM_WCH + t * 200 + (s - 24) * 8 + 4]);
        acc = fmaf(a0.x, w0.x, acc); acc = fmaf(a0.y, w0.y, acc);
        acc = fmaf(a0.z, w0.z, acc); acc = fmaf(a0.w, w0.w, acc);
        acc = fmaf(a1.x, w1.x, acc); acc = fmaf(a1.y, w1.y, acc);
        acc = fmaf(a1.z, w1.z, acc); acc = fmaf(a1.w, w1.w, acc);
    }
    sh[SM_H + ls * 16 + t] = fmaxf(acc, 0.f);
    __syncwarp();

    {
        float lg = 0.f;
        if (t < 10) {
            const float4* w  = reinterpret_cast<const float4*>(&sh[SM_F2W + t * 16]);
            const float4* hh = reinterpret_cast<const float4*>(&sh[SM_H + ls * 16]);
            float4 h0 = hh[0], h1 = hh[1], h2 = hh[2], h3 = hh[3];
            float4 w0 = w[0], w1 = w[1], w2 = w[2], w3 = w[3];
            lg = fmaf(h0.x, w0.x, lg); lg = fmaf(h0.y, w0.y, lg);
            lg = fmaf(h0.z, w0.z, lg); lg = fmaf(h0.w, w0.w, lg);
            lg = fmaf(h1.x, w1.x, lg); lg = fmaf(h1.y, w1.y, lg);
            lg = fmaf(h1.z, w1.z, lg); lg = fmaf(h1.w, w1.w, lg);
            lg = fmaf(h2.x, w2.x, lg); lg = fmaf(h2.y, w2.y, lg);
            lg = fmaf(h2.z, w2.z, lg); lg = fmaf(h2.w, w2.w, lg);
            lg = fmaf(h3.x, w3.x, lg); lg = fmaf(h3.y, w3.y, lg);
            lg = fmaf(h3.z, w3.z, lg); lg = fmaf(h3.w, w3.w, lg);
            lg += sh[SM_F2B + t];
        }
        sh[SM_LG + ls * 16 + t] = lg;
    }
    __syncwarp();

    if (t == 0 && b < B) {
        const float* lrow = &sh[SM_LG + ls * 16];
        float m = lrow[0];
#pragma unroll
        for (int c = 1; c < 10; c++) m = fmaxf(m, lrow[c]);
        float ex[10], sum = 0.f;
#pragma unroll
        for (int c = 0; c < 10; c++) { ex[c] = __expf(lrow[c] - m); sum += ex[c]; }
        float inv = 1.f / sum;
        float* o = out + (size_t)b * 10;
#pragma unroll
        for (int c = 0; c < 10; c++) o[c] = ex[c] * inv;
    }
}

extern "C" void kernel_launch(void* const* d_in, const int* in_sizes, int n_in,
                              void* d_out, int out_size) {
    const float* x   = (const float*)d_in[0];
    const float* pe  = (const float*)d_in[1];
    const float* WQ1 = (const float*)d_in[2];
    const float* WK1 = (const float*)d_in[3];
    const float* WV1 = (const float*)d_in[4];
    const float* WQ2 = (const float*)d_in[5];
    const float* WK2 = (const float*)d_in[6];
    const float* WV2 = (const float*)d_in[7];
    const float* f1w = (const float*)d_in[8];
    const float* f1b = (const float*)d_in[9];
    const float* f2w = (const float*)d_in[10];
    const float* f2b = (const float*)d_in[11];
    float* out = (float*)d_out;

    int B = in_sizes[0] / (3 * 28 * 28);
    int grid = (B + GRP - 1) / GRP;
    size_t smem = (size_t)SM_TOT * sizeof(float);

    cudaFuncSetAttribute(vit_fused_kernel,
                         cudaFuncAttributeMaxDynamicSharedMemorySize, (int)smem);
    vit_fused_kernel<<<grid, NTHR, smem>>>(x, pe, WQ1, WK1, WV1, WQ2, WK2, WV2,
                                           f1w, f1b, f2w, f2b, out, B);
}

// round 9
// speedup vs baseline: 2.4230x; 1.1896x over previous
#include <cuda_runtime.h>
#include <math.h>

// ViT fused R9 = R6 architecture + race-free deferred V writes + FIXED two-half
// fc1w staging (R6/R8 staged 392-float rows at 200-float stride -> overlap bug).
// Warp-per-patch projections (weights gmem->regs, amortized over 16 samples),
// shuffle-free gram via Q/K smem staging. 72.5KB smem -> 3 CTAs/SM.

#define GRP  16
#define NTHR 256

static constexpr int SM_PB  = 0;        // 16*784 = 12544  (patches -> V1 -> tok2 -> V2 -> tok3)
static constexpr int SM_PE  = 12544;    // 784
static constexpr int SM_QB  = 13328;    // 2048  Qbuf (fc1w half-staging 3200 spans QB+KB)
static constexpr int SM_KB  = 15376;    // 2048  Kbuf
static constexpr int SM_F2W = 17424;    // 160
static constexpr int SM_F1B = 17584;    // 16
static constexpr int SM_F2B = 17600;    // 16
static constexpr int SM_H   = 17616;    // 256
static constexpr int SM_LG  = 17872;    // 256
static constexpr int SM_TOT = 18128;    // 72512 bytes

__device__ __forceinline__ float dot4(float4 w, float4 a, float acc) {
    acc = fmaf(w.x, a.x, acc); acc = fmaf(w.y, a.y, acc);
    acc = fmaf(w.z, a.z, acc); return fmaf(w.w, a.w, acc);
}

__global__ __launch_bounds__(NTHR, 3)
void vit_fused_kernel(
    const float* __restrict__ x, const float* __restrict__ pos_emb,
    const float* __restrict__ WQ1, const float* __restrict__ WK1, const float* __restrict__ WV1,
    const float* __restrict__ WQ2, const float* __restrict__ WK2, const float* __restrict__ WV2,
    const float* __restrict__ fc1w, const float* __restrict__ fc1b,
    const float* __restrict__ fc2w, const float* __restrict__ fc2b,
    float* __restrict__ out, int B)
{
    extern __shared__ float sh[];
    const int tid  = threadIdx.x;
    const int lane = tid & 31;
    const int wrp  = tid >> 5;          // 0..7 : patch slot in P-phases
    const int t    = tid & 15;          // dim within sample
    const int ls   = tid >> 4;          // sample slot
    const int b0   = blockIdx.x * GRP;
    const int b    = b0 + ls;
    const float INV7 = 0.14285714285714285f;
    float* myrow = &sh[SM_PB + ls * 784];

    // ---------------- phase 0: patchify + constants ----------------
    for (int idx = tid; idx < GRP * 784; idx += NTHR) {
        int lsi = idx / 784, pix = idx - lsi * 784;
        int bb = b0 + lsi;
        float g = 0.f;
        if (bb < B) {
            const float* xp = x + (size_t)bb * 2352 + pix;
            g = 0.299f * xp[0] + 0.587f * xp[784] + 0.114f * xp[1568];
        }
        int y = pix / 28, xx = pix - y * 28;
        sh[SM_PB + lsi * 784 + ((y >> 2) * 7 + (xx >> 2)) * 16 + (y & 3) * 4 + (xx & 3)] = g;
    }
    for (int idx = tid; idx < 784; idx += NTHR) sh[SM_PE + idx] = pos_emb[idx];
    if (tid < 160) sh[SM_F2W + tid] = fc2w[tid];
    if (tid < 16)  sh[SM_F1B + tid] = fc1b[tid];
    if (tid < 10)  sh[SM_F2B + tid] = fc2b[tid];

    // ---------------- layer 1: chunks of 8 patches ----------------
    float S1[16];
#pragma unroll
    for (int e = 0; e < 16; e++) S1[e] = 0.f;

#pragma unroll 1
    for (int c0 = 0; c0 < 49; c0 += 8) {
        const int np = min(8, 49 - c0);
        __syncthreads();
        float vacc[16];
        const int s = c0 + wrp;
        // ---- P-phase ----
        if (wrp < np) {
            const int row = lane & 15;
            // pass A: lanes 0-15 Q rows, 16-31 K rows (QB/KB read only after syncthreads)
            {
                const float4* pe4 = reinterpret_cast<const float4*>(&sh[SM_PE + s * 16]);
                float4 p0 = pe4[0], p1 = pe4[1], p2 = pe4[2], p3 = pe4[3];
                const float* Wp = ((lane < 16) ? WQ1 : WK1) + s * 512 + row * 32;
                const float4* W4 = reinterpret_cast<const float4*>(Wp);
                float4 w0 = W4[0], w1 = W4[1], w2 = W4[2], w3 = W4[3];
                float pe_acc = dot4(W4[7], p3, dot4(W4[6], p2, dot4(W4[5], p1, dot4(W4[4], p0, 0.f))));
                const float scl = (lane < 16) ? INV7 : 1.f;
                const int dst = ((lane < 16) ? SM_QB : SM_KB) + wrp * 16 + row;
#pragma unroll 4
                for (int i = 0; i < 16; i++) {
                    const float4* tk = reinterpret_cast<const float4*>(&sh[SM_PB + i * 784 + s * 16]);
                    float acc = dot4(w3, tk[3], dot4(w2, tk[2], dot4(w1, tk[1], dot4(w0, tk[0], pe_acc))));
                    sh[dst + i * 128] = acc * scl;
                }
            }
            // pass B: lanes 0-15 compute V rows into regs (no smem writes yet)
            if (lane < 16) {
                const float4* pe4 = reinterpret_cast<const float4*>(&sh[SM_PE + s * 16]);
                float4 p0 = pe4[0], p1 = pe4[1], p2 = pe4[2], p3 = pe4[3];
                const float4* W4 = reinterpret_cast<const float4*>(WV1 + s * 512 + row * 32);
                float4 w0 = W4[0], w1 = W4[1], w2 = W4[2], w3 = W4[3];
                float pe_acc = dot4(W4[7], p3, dot4(W4[6], p2, dot4(W4[5], p1, dot4(W4[4], p0, 0.f))));
#pragma unroll 4
                for (int i = 0; i < 16; i++) {
                    const float4* tk = reinterpret_cast<const float4*>(&sh[SM_PB + i * 784 + s * 16]);
                    vacc[i] = dot4(w3, tk[3], dot4(w2, tk[2], dot4(w1, tk[1], dot4(w0, tk[0], pe_acc))));
                }
            }
        }
        __syncwarp();   // all lanes' patch-row reads complete before V overwrites
        if (wrp < np && lane < 16) {
            const int row = lane & 15;
#pragma unroll
            for (int i = 0; i < 16; i++)
                sh[SM_PB + i * 784 + s * 16 + row] = vacc[i];
        }
        __syncthreads();
        // ---- G-phase: warp = 2 samples, no shuffles ----
#pragma unroll 1
        for (int j = 0; j < np; j++) {
            float q = sh[SM_QB + ls * 128 + j * 16 + t];
            const float4* kr = reinterpret_cast<const float4*>(&sh[SM_KB + ls * 128 + j * 16]);
            float4 k0 = kr[0], k1 = kr[1], k2 = kr[2], k3 = kr[3];
            S1[0]  = fmaf(q, k0.x, S1[0]);  S1[1]  = fmaf(q, k0.y, S1[1]);
            S1[2]  = fmaf(q, k0.z, S1[2]);  S1[3]  = fmaf(q, k0.w, S1[3]);
            S1[4]  = fmaf(q, k1.x, S1[4]);  S1[5]  = fmaf(q, k1.y, S1[5]);
            S1[6]  = fmaf(q, k1.z, S1[6]);  S1[7]  = fmaf(q, k1.w, S1[7]);
            S1[8]  = fmaf(q, k2.x, S1[8]);  S1[9]  = fmaf(q, k2.y, S1[9]);
            S1[10] = fmaf(q, k2.z, S1[10]); S1[11] = fmaf(q, k2.w, S1[11]);
            S1[12] = fmaf(q, k3.x, S1[12]); S1[13] = fmaf(q, k3.y, S1[13]);
            S1[14] = fmaf(q, k3.z, S1[14]); S1[15] = fmaf(q, k3.w, S1[15]);
        }
    }

    // ---------------- A1: tok2[s,d] = sum_e S1[d,e] V[s,e] (in place) ----------------
#pragma unroll 1
    for (int s = 0; s < 49; s++) {
        const float4* vr = reinterpret_cast<const float4*>(&myrow[s * 16]);
        float4 v0 = vr[0], v1 = vr[1], v2 = vr[2], v3 = vr[3];
        float a0 = 0.f, a1 = 0.f;
        a0 = fmaf(S1[0],  v0.x, a0); a1 = fmaf(S1[1],  v0.y, a1);
        a0 = fmaf(S1[2],  v0.z, a0); a1 = fmaf(S1[3],  v0.w, a1);
        a0 = fmaf(S1[4],  v1.x, a0); a1 = fmaf(S1[5],  v1.y, a1);
        a0 = fmaf(S1[6],  v1.z, a0); a1 = fmaf(S1[7],  v1.w, a1);
        a0 = fmaf(S1[8],  v2.x, a0); a1 = fmaf(S1[9],  v2.y, a1);
        a0 = fmaf(S1[10], v2.z, a0); a1 = fmaf(S1[11], v2.w, a1);
        a0 = fmaf(S1[12], v3.x, a0); a1 = fmaf(S1[13], v3.y, a1);
        a0 = fmaf(S1[14], v3.z, a0); a1 = fmaf(S1[15], v3.w, a1);
        __syncwarp();
        myrow[s * 16 + t] = a0 + a1;
    }
    __syncwarp();

    // ---------------- softmax1 ----------------
#pragma unroll 1
    for (int s = t; s < 49; s += 16) {
        float4* row = reinterpret_cast<float4*>(&myrow[s * 16]);
        float4 r0 = row[0], r1 = row[1], r2 = row[2], r3 = row[3];
        float m = fmaxf(fmaxf(fmaxf(r0.x, r0.y), fmaxf(r0.z, r0.w)),
                        fmaxf(fmaxf(r1.x, r1.y), fmaxf(r1.z, r1.w)));
        m = fmaxf(m, fmaxf(fmaxf(fmaxf(r2.x, r2.y), fmaxf(r2.z, r2.w)),
                           fmaxf(fmaxf(r3.x, r3.y), fmaxf(r3.z, r3.w))));
        r0.x = __expf(r0.x - m); r0.y = __expf(r0.y - m); r0.z = __expf(r0.z - m); r0.w = __expf(r0.w - m);
        r1.x = __expf(r1.x - m); r1.y = __expf(r1.y - m); r1.z = __expf(r1.z - m); r1.w = __expf(r1.w - m);
        r2.x = __expf(r2.x - m); r2.y = __expf(r2.y - m); r2.z = __expf(r2.z - m); r2.w = __expf(r2.w - m);
        r3.x = __expf(r3.x - m); r3.y = __expf(r3.y - m); r3.z = __expf(r3.z - m); r3.w = __expf(r3.w - m);
        float sum = (r0.x + r0.y + r0.z + r0.w) + (r1.x + r1.y + r1.z + r1.w)
                  + (r2.x + r2.y + r2.z + r2.w) + (r3.x + r3.y + r3.z + r3.w);
        float inv = 1.f / sum;
        r0.x *= inv; r0.y *= inv; r0.z *= inv; r0.w *= inv;
        r1.x *= inv; r1.y *= inv; r1.z *= inv; r1.w *= inv;
        r2.x *= inv; r2.y *= inv; r2.z *= inv; r2.w *= inv;
        r3.x *= inv; r3.y *= inv; r3.z *= inv; r3.w *= inv;
        row[0] = r0; row[1] = r1; row[2] = r2; row[3] = r3;
    }

    // ---------------- layer 2: chunks of 8 patches ----------------
    float S2[8];
#pragma unroll
    for (int e = 0; e < 8; e++) S2[e] = 0.f;

#pragma unroll 1
    for (int c0 = 0; c0 < 49; c0 += 8) {
        const int np = min(8, 49 - c0);
        __syncthreads();
        float vacc[16];
        const int s = c0 + wrp;
        if (wrp < np && lane < 24) {
            const int role = lane >> 3;      // 0:Q 1:K 2:V
            const int r    = lane & 7;
            const float* Wp = ((role == 0) ? WQ2 : (role == 1) ? WK2 : WV2) + s * 128 + r * 16;
            const float4* W4 = reinterpret_cast<const float4*>(Wp);
            float4 w0 = W4[0], w1 = W4[1], w2 = W4[2], w3 = W4[3];
            if (role < 2) {
                const float scl = (role == 0) ? INV7 : 1.f;
                const int dst = ((role == 0) ? SM_QB : SM_KB) + wrp * 8 + r;
#pragma unroll 4
                for (int i = 0; i < 16; i++) {
                    const float4* tk = reinterpret_cast<const float4*>(&sh[SM_PB + i * 784 + s * 16]);
                    float acc = dot4(w3, tk[3], dot4(w2, tk[2], dot4(w1, tk[1], dot4(w0, tk[0], 0.f))));
                    sh[dst + i * 64] = acc * scl;
                }
            } else {
                // V: defer (writes over tok2 rows that Q/K lanes still read)
#pragma unroll 4
                for (int i = 0; i < 16; i++) {
                    const float4* tk = reinterpret_cast<const float4*>(&sh[SM_PB + i * 784 + s * 16]);
                    vacc[i] = dot4(w3, tk[3], dot4(w2, tk[2], dot4(w1, tk[1], dot4(w0, tk[0], 0.f))));
                }
            }
        }
        __syncwarp();   // all tok2 reads complete before V2 overwrites
        if (wrp < np && lane >= 16 && lane < 24) {
            const int r = lane & 7;
#pragma unroll
            for (int i = 0; i < 16; i++)
                sh[SM_PB + i * 784 + s * 16 + r] = vacc[i];
        }
        __syncthreads();
        if (t < 8) {
#pragma unroll 1
            for (int j = 0; j < np; j++) {
                float q2 = sh[SM_QB + ls * 64 + j * 8 + t];
                const float4* kr = reinterpret_cast<const float4*>(&sh[SM_KB + ls * 64 + j * 8]);
                float4 k0 = kr[0], k1 = kr[1];
                S2[0] = fmaf(q2, k0.x, S2[0]); S2[1] = fmaf(q2, k0.y, S2[1]);
                S2[2] = fmaf(q2, k0.z, S2[2]); S2[3] = fmaf(q2, k0.w, S2[3]);
                S2[4] = fmaf(q2, k1.x, S2[4]); S2[5] = fmaf(q2, k1.y, S2[5]);
                S2[6] = fmaf(q2, k1.z, S2[6]); S2[7] = fmaf(q2, k1.w, S2[7]);
            }
        }
    }

    // ---------------- A2: tok3 (in place, t<8) ----------------
#pragma unroll 1
    for (int s = 0; s < 49; s++) {
        float a = 0.f;
        if (t < 8) {
            const float4* vr = reinterpret_cast<const float4*>(&myrow[s * 16]);
            float4 v0 = vr[0], v1 = vr[1];
            a = fmaf(S2[0], v0.x, a); a = fmaf(S2[1], v0.y, a);
            a = fmaf(S2[2], v0.z, a); a = fmaf(S2[3], v0.w, a);
            a = fmaf(S2[4], v1.x, a); a = fmaf(S2[5], v1.y, a);
            a = fmaf(S2[6], v1.z, a); a = fmaf(S2[7], v1.w, a);
        }
        __syncwarp();
        if (t < 8) myrow[s * 16 + t] = a;
    }
    __syncwarp();

    // ---------------- softmax2 ----------------
#pragma unroll 1
    for (int s = t; s < 49; s += 16) {
        float4* row = reinterpret_cast<float4*>(&myrow[s * 16]);
        float4 r0 = row[0], r1 = row[1];
        float m = fmaxf(fmaxf(fmaxf(r0.x, r0.y), fmaxf(r0.z, r0.w)),
                        fmaxf(fmaxf(r1.x, r1.y), fmaxf(r1.z, r1.w)));
        r0.x = __expf(r0.x - m); r0.y = __expf(r0.y - m); r0.z = __expf(r0.z - m); r0.w = __expf(r0.w - m);
        r1.x = __expf(r1.x - m); r1.y = __expf(r1.y - m); r1.z = __expf(r1.z - m); r1.w = __expf(r1.w - m);
        float sum = (r0.x + r0.y + r0.z + r0.w) + (r1.x + r1.y + r1.z + r1.w);
        float inv = 1.f / sum;
        r0.x *= inv; r0.y *= inv; r0.z *= inv; r0.w *= inv;
        r1.x *= inv; r1.y *= inv; r1.z *= inv; r1.w *= inv;
        row[0] = r0; row[1] = r1;
    }

    // ---------------- FC head: fc1w staged in TWO K-halves (stride 200, no overlap) ----------------
    float acc = sh[SM_F1B + t];
    // half 0: s in [0,24)  -> weight cols [0,192), 48 float4 per row
    __syncthreads();
    for (int idx = tid; idx < 768; idx += NTHR) {    // 16 rows x 48 float4
        int j = idx / 48, c4 = idx - j * 48;
        *reinterpret_cast<float4*>(&sh[SM_QB + j * 200 + c4 * 4]) =
            *reinterpret_cast<const float4*>(&fc1w[j * 392 + c4 * 4]);
    }
    __syncthreads();
#pragma unroll 1
    for (int s = 0; s < 24; s++) {
        float4 a0 = *reinterpret_cast<const float4*>(&myrow[s * 16]);
        float4 a1 = *reinterpret_cast<const float4*>(&myrow[s * 16 + 4]);
        float4 w0 = *reinterpret_cast<const float4*>(&sh[SM_QB + t * 200 + s * 8]);
        float4 w1 = *reinterpret_cast<const float4*>(&sh[SM_QB + t * 200 + s * 8 + 4]);
        acc = dot4(w0, a0, acc);
        acc = dot4(w1, a1, acc);
    }
    // half 1: s in [24,49) -> weight cols [192,392), 50 float4 per row
    __syncthreads();
    for (int idx = tid; idx < 800; idx += NTHR) {    // 16 rows x 50 float4
        int j = idx / 50, c4 = idx - j * 50;
        *reinterpret_cast<float4*>(&sh[SM_QB + j * 200 + c4 * 4]) =
            *reinterpret_cast<const float4*>(&fc1w[j * 392 + 192 + c4 * 4]);
    }
    __syncthreads();
#pragma unroll 1
    for (int s = 24; s < 49; s++) {
        float4 a0 = *reinterpret_cast<const float4*>(&myrow[s * 16]);
        float4 a1 = *reinterpret_cast<const float4*>(&myrow[s * 16 + 4]);
        float4 w0 = *reinterpret_cast<const float4*>(&sh[SM_QB + t * 200 + (s - 24) * 8]);
        float4 w1 = *reinterpret_cast<const float4*>(&sh[SM_QB + t * 200 + (s - 24) * 8 + 4]);
        acc = dot4(w0, a0, acc);
        acc = dot4(w1, a1, acc);
    }
    sh[SM_H + ls * 16 + t] = fmaxf(acc, 0.f);
    __syncwarp();

    {
        float lg = 0.f;
        if (t < 10) {
            const float4* w  = reinterpret_cast<const float4*>(&sh[SM_F2W + t * 16]);
            const float4* hh = reinterpret_cast<const float4*>(&sh[SM_H + ls * 16]);
            lg = dot4(w[0], hh[0], lg); lg = dot4(w[1], hh[1], lg);
            lg = dot4(w[2], hh[2], lg); lg = dot4(w[3], hh[3], lg);
            lg += sh[SM_F2B + t];
        }
        sh[SM_LG + ls * 16 + t] = lg;
    }
    __syncwarp();

    if (t == 0 && b < B) {
        const float* lrow = &sh[SM_LG + ls * 16];
        float m = lrow[0];
#pragma unroll
        for (int c = 1; c < 10; c++) m = fmaxf(m, lrow[c]);
        float ex[10], sum = 0.f;
#pragma unroll
        for (int c = 0; c < 10; c++) { ex[c] = __expf(lrow[c] - m); sum += ex[c]; }
        float inv = 1.f / sum;
        float* o = out + (size_t)b * 10;
#pragma unroll
        for (int c = 0; c < 10; c++) o[c] = ex[c] * inv;
    }
}

extern "C" void kernel_launch(void* const* d_in, const int* in_sizes, int n_in,
                              void* d_out, int out_size) {
    const float* x   = (const float*)d_in[0];
    const float* pe  = (const float*)d_in[1];
    const float* WQ1 = (const float*)d_in[2];
    const float* WK1 = (const float*)d_in[3];
    const float* WV1 = (const float*)d_in[4];
    const float* WQ2 = (const float*)d_in[5];
    const float* WK2 = (const float*)d_in[6];
    const float* WV2 = (const float*)d_in[7];
    const float* f1w = (const float*)d_in[8];
    const float* f1b = (const float*)d_in[9];
    const float* f2w = (const float*)d_in[10];
    const float* f2b = (const float*)d_in[11];
    float* out = (float*)d_out;

    int B = in_sizes[0] / (3 * 28 * 28);
    int grid = (B + GRP - 1) / GRP;
    size_t smem = (size_t)SM_TOT * sizeof(float);

    cudaFuncSetAttribute(vit_fused_kernel,
                         cudaFuncAttributeMaxDynamicSharedMemorySize, (int)smem);
    vit_fused_kernel<<<grid, NTHR, smem>>>(x, pe, WQ1, WK1, WV1, WQ2, WK2, WV2,
                                           f1w, f1b, f2w, f2b, out, B);
}

// round 10
// speedup vs baseline: 2.4549x; 1.0132x over previous
#include <cuda_runtime.h>
#include <math.h>

// ViT fused R10 = R9 + full-width V passes + split layer-2 gram + grouped A1/A2 writes.
// Warp-per-patch projections (weights gmem->regs, amortized over 16 samples),
// shuffle-free gram via Q/K smem staging. 72.5KB smem -> 3 CTAs/SM.

#define GRP  16
#define NTHR 256

static constexpr int SM_PB  = 0;        // 16*784 = 12544
static constexpr int SM_PE  = 12544;    // 784
static constexpr int SM_QB  = 13328;    // 2048  (fc1w half-staging 3200 spans QB+KB)
static constexpr int SM_KB  = 15376;    // 2048
static constexpr int SM_F2W = 17424;    // 160
static constexpr int SM_F1B = 17584;    // 16
static constexpr int SM_F2B = 17600;    // 16
static constexpr int SM_H   = 17616;    // 256
static constexpr int SM_LG  = 17872;    // 256
static constexpr int SM_TOT = 18128;    // 72512 bytes

__device__ __forceinline__ float dot4(float4 w, float4 a, float acc) {
    acc = fmaf(w.x, a.x, acc); acc = fmaf(w.y, a.y, acc);
    acc = fmaf(w.z, a.z, acc); return fmaf(w.w, a.w, acc);
}

__global__ __launch_bounds__(NTHR, 3)
void vit_fused_kernel(
    const float* __restrict__ x, const float* __restrict__ pos_emb,
    const float* __restrict__ WQ1, const float* __restrict__ WK1, const float* __restrict__ WV1,
    const float* __restrict__ WQ2, const float* __restrict__ WK2, const float* __restrict__ WV2,
    const float* __restrict__ fc1w, const float* __restrict__ fc1b,
    const float* __restrict__ fc2w, const float* __restrict__ fc2b,
    float* __restrict__ out, int B)
{
    extern __shared__ float sh[];
    const int tid  = threadIdx.x;
    const int lane = tid & 31;
    const int wrp  = tid >> 5;          // 0..7 : patch slot in P-phases
    const int t    = tid & 15;          // dim within sample
    const int ls   = tid >> 4;          // sample slot
    const int b0   = blockIdx.x * GRP;
    const int b    = b0 + ls;
    const float INV7 = 0.14285714285714285f;
    float* myrow = &sh[SM_PB + ls * 784];

    // ---------------- phase 0: patchify + constants ----------------
    for (int idx = tid; idx < GRP * 784; idx += NTHR) {
        int lsi = idx / 784, pix = idx - lsi * 784;
        int bb = b0 + lsi;
        float g = 0.f;
        if (bb < B) {
            const float* xp = x + (size_t)bb * 2352 + pix;
            g = 0.299f * xp[0] + 0.587f * xp[784] + 0.114f * xp[1568];
        }
        int y = pix / 28, xx = pix - y * 28;
        sh[SM_PB + lsi * 784 + ((y >> 2) * 7 + (xx >> 2)) * 16 + (y & 3) * 4 + (xx & 3)] = g;
    }
    for (int idx = tid; idx < 784; idx += NTHR) sh[SM_PE + idx] = pos_emb[idx];
    if (tid < 160) sh[SM_F2W + tid] = fc2w[tid];
    if (tid < 16)  sh[SM_F1B + tid] = fc1b[tid];
    if (tid < 10)  sh[SM_F2B + tid] = fc2b[tid];

    // ---------------- layer 1: chunks of 8 patches ----------------
    float S1[16];
#pragma unroll
    for (int e = 0; e < 16; e++) S1[e] = 0.f;

#pragma unroll 1
    for (int c0 = 0; c0 < 49; c0 += 8) {
        const int np = min(8, 49 - c0);
        __syncthreads();
        float vacc[8];
        const int s = c0 + wrp;
        const int row = lane & 15;
        const int i0v = (lane >> 4) * 8;     // V-pass sample half
        // ---- P-phase ----
        if (wrp < np) {
            // pass A: lanes 0-15 Q rows, 16-31 K rows; all 16 samples
            {
                const float4* pe4 = reinterpret_cast<const float4*>(&sh[SM_PE + s * 16]);
                float4 p0 = pe4[0], p1 = pe4[1], p2 = pe4[2], p3 = pe4[3];
                const float* Wp = ((lane < 16) ? WQ1 : WK1) + s * 512 + row * 32;
                const float4* W4 = reinterpret_cast<const float4*>(Wp);
                float4 w0 = W4[0], w1 = W4[1], w2 = W4[2], w3 = W4[3];
                float pe_acc = dot4(W4[7], p3, dot4(W4[6], p2, dot4(W4[5], p1, dot4(W4[4], p0, 0.f))));
                const float scl = (lane < 16) ? INV7 : 1.f;
                const int dst = ((lane < 16) ? SM_QB : SM_KB) + wrp * 16 + row;
#pragma unroll 4
                for (int i = 0; i < 16; i++) {
                    const float4* tk = reinterpret_cast<const float4*>(&sh[SM_PB + i * 784 + s * 16]);
                    float acc = dot4(w3, tk[3], dot4(w2, tk[2], dot4(w1, tk[1], dot4(w0, tk[0], pe_acc))));
                    sh[dst + i * 128] = acc * scl;
                }
            }
            // pass B: V row = lane&15, sample half by lane>>4 (full 32 lanes)
            {
                const float4* pe4 = reinterpret_cast<const float4*>(&sh[SM_PE + s * 16]);
                float4 p0 = pe4[0], p1 = pe4[1], p2 = pe4[2], p3 = pe4[3];
                const float4* W4 = reinterpret_cast<const float4*>(WV1 + s * 512 + row * 32);
                float4 w0 = W4[0], w1 = W4[1], w2 = W4[2], w3 = W4[3];
                float pe_acc = dot4(W4[7], p3, dot4(W4[6], p2, dot4(W4[5], p1, dot4(W4[4], p0, 0.f))));
#pragma unroll
                for (int ii = 0; ii < 8; ii++) {
                    const int i = i0v + ii;
                    const float4* tk = reinterpret_cast<const float4*>(&sh[SM_PB + i * 784 + s * 16]);
                    vacc[ii] = dot4(w3, tk[3], dot4(w2, tk[2], dot4(w1, tk[1], dot4(w0, tk[0], pe_acc))));
                }
            }
        }
        __syncwarp();   // all patch-row reads complete before V overwrites
        if (wrp < np) {
#pragma unroll
            for (int ii = 0; ii < 8; ii++)
                sh[SM_PB + (i0v + ii) * 784 + s * 16 + row] = vacc[ii];
        }
        __syncthreads();
        // ---- G-phase: warp = 2 samples, no shuffles ----
#pragma unroll 1
        for (int j = 0; j < np; j++) {
            float q = sh[SM_QB + ls * 128 + j * 16 + t];
            const float4* kr = reinterpret_cast<const float4*>(&sh[SM_KB + ls * 128 + j * 16]);
            float4 k0 = kr[0], k1 = kr[1], k2 = kr[2], k3 = kr[3];
            S1[0]  = fmaf(q, k0.x, S1[0]);  S1[1]  = fmaf(q, k0.y, S1[1]);
            S1[2]  = fmaf(q, k0.z, S1[2]);  S1[3]  = fmaf(q, k0.w, S1[3]);
            S1[4]  = fmaf(q, k1.x, S1[4]);  S1[5]  = fmaf(q, k1.y, S1[5]);
            S1[6]  = fmaf(q, k1.z, S1[6]);  S1[7]  = fmaf(q, k1.w, S1[7]);
            S1[8]  = fmaf(q, k2.x, S1[8]);  S1[9]  = fmaf(q, k2.y, S1[9]);
            S1[10] = fmaf(q, k2.z, S1[10]); S1[11] = fmaf(q, k2.w, S1[11]);
            S1[12] = fmaf(q, k3.x, S1[12]); S1[13] = fmaf(q, k3.y, S1[13]);
            S1[14] = fmaf(q, k3.z, S1[14]); S1[15] = fmaf(q, k3.w, S1[15]);
        }
    }

    // ---------------- A1: tok2[s,d] = sum_e S1[d,e] V[s,e] (grouped, in place) ----------------
#pragma unroll 1
    for (int sb = 0; sb < 49; sb += 7) {
        float a[7];
#pragma unroll
        for (int u2 = 0; u2 < 7; u2++) {
            const float4* vr = reinterpret_cast<const float4*>(&myrow[(sb + u2) * 16]);
            float4 v0 = vr[0], v1 = vr[1], v2 = vr[2], v3 = vr[3];
            float a0 = 0.f, a1 = 0.f;
            a0 = fmaf(S1[0],  v0.x, a0); a1 = fmaf(S1[1],  v0.y, a1);
            a0 = fmaf(S1[2],  v0.z, a0); a1 = fmaf(S1[3],  v0.w, a1);
            a0 = fmaf(S1[4],  v1.x, a0); a1 = fmaf(S1[5],  v1.y, a1);
            a0 = fmaf(S1[6],  v1.z, a0); a1 = fmaf(S1[7],  v1.w, a1);
            a0 = fmaf(S1[8],  v2.x, a0); a1 = fmaf(S1[9],  v2.y, a1);
            a0 = fmaf(S1[10], v2.z, a0); a1 = fmaf(S1[11], v2.w, a1);
            a0 = fmaf(S1[12], v3.x, a0); a1 = fmaf(S1[13], v3.y, a1);
            a0 = fmaf(S1[14], v3.z, a0); a1 = fmaf(S1[15], v3.w, a1);
            a[u2] = a0 + a1;
        }
        __syncwarp();
#pragma unroll
        for (int u2 = 0; u2 < 7; u2++) myrow[(sb + u2) * 16 + t] = a[u2];
        __syncwarp();
    }

    // ---------------- softmax1 ----------------
#pragma unroll 1
    for (int s = t; s < 49; s += 16) {
        float4* row = reinterpret_cast<float4*>(&myrow[s * 16]);
        float4 r0 = row[0], r1 = row[1], r2 = row[2], r3 = row[3];
        float m = fmaxf(fmaxf(fmaxf(r0.x, r0.y), fmaxf(r0.z, r0.w)),
                        fmaxf(fmaxf(r1.x, r1.y), fmaxf(r1.z, r1.w)));
        m = fmaxf(m, fmaxf(fmaxf(fmaxf(r2.x, r2.y), fmaxf(r2.z, r2.w)),
                           fmaxf(fmaxf(r3.x, r3.y), fmaxf(r3.z, r3.w))));
        r0.x = __expf(r0.x - m); r0.y = __expf(r0.y - m); r0.z = __expf(r0.z - m); r0.w = __expf(r0.w - m);
        r1.x = __expf(r1.x - m); r1.y = __expf(r1.y - m); r1.z = __expf(r1.z - m); r1.w = __expf(r1.w - m);
        r2.x = __expf(r2.x - m); r2.y = __expf(r2.y - m); r2.z = __expf(r2.z - m); r2.w = __expf(r2.w - m);
        r3.x = __expf(r3.x - m); r3.y = __expf(r3.y - m); r3.z = __expf(r3.z - m); r3.w = __expf(r3.w - m);
        float sum = (r0.x + r0.y + r0.z + r0.w) + (r1.x + r1.y + r1.z + r1.w)
                  + (r2.x + r2.y + r2.z + r2.w) + (r3.x + r3.y + r3.z + r3.w);
        float inv = 1.f / sum;
        r0.x *= inv; r0.y *= inv; r0.z *= inv; r0.w *= inv;
        r1.x *= inv; r1.y *= inv; r1.z *= inv; r1.w *= inv;
        r2.x *= inv; r2.y *= inv; r2.z *= inv; r2.w *= inv;
        r3.x *= inv; r3.y *= inv; r3.z *= inv; r3.w *= inv;
        row[0] = r0; row[1] = r1; row[2] = r2; row[3] = r3;
    }

    // ---------------- layer 2: chunks of 8 patches ----------------
    float S2[8];
#pragma unroll
    for (int e = 0; e < 8; e++) S2[e] = 0.f;

#pragma unroll 1
    for (int c0 = 0; c0 < 49; c0 += 8) {
        const int np = min(8, 49 - c0);
        __syncthreads();
        float vacc[4];
        const int s = c0 + wrp;
        const int rV  = lane & 7;
        const int i0V = (lane >> 3) * 4;     // V-pass sample quarter
        if (wrp < np) {
            // pass A: 16 rows (8Q+8K) x two sample halves -> full 32 lanes
            {
                const int row16 = lane & 15;
                const int i0A = (lane >> 4) * 8;
                const bool isQ = (row16 < 8);
                const int r = isQ ? row16 : row16 - 8;
                const float* Wp = (isQ ? WQ2 : WK2) + s * 128 + r * 16;
                const float4* W4 = reinterpret_cast<const float4*>(Wp);
                float4 w0 = W4[0], w1 = W4[1], w2 = W4[2], w3 = W4[3];
                const float scl = isQ ? INV7 : 1.f;
                const int dst = (isQ ? SM_QB : SM_KB) + wrp * 8 + r;
#pragma unroll
                for (int ii = 0; ii < 8; ii++) {
                    const int i = i0A + ii;
                    const float4* tk = reinterpret_cast<const float4*>(&sh[SM_PB + i * 784 + s * 16]);
                    float acc = dot4(w3, tk[3], dot4(w2, tk[2], dot4(w1, tk[1], dot4(w0, tk[0], 0.f))));
                    sh[dst + i * 64] = acc * scl;
                }
            }
            // pass B: V 8 rows x four sample quarters -> full 32 lanes (deferred)
            {
                const float4* W4 = reinterpret_cast<const float4*>(WV2 + s * 128 + rV * 16);
                float4 w0 = W4[0], w1 = W4[1], w2 = W4[2], w3 = W4[3];
#pragma unroll
                for (int ii = 0; ii < 4; ii++) {
                    const int i = i0V + ii;
                    const float4* tk = reinterpret_cast<const float4*>(&sh[SM_PB + i * 784 + s * 16]);
                    vacc[ii] = dot4(w3, tk[3], dot4(w2, tk[2], dot4(w1, tk[1], dot4(w0, tk[0], 0.f))));
                }
            }
        }
        __syncwarp();   // all tok2 reads complete before V2 overwrites
        if (wrp < np) {
#pragma unroll
            for (int ii = 0; ii < 4; ii++)
                sh[SM_PB + (i0V + ii) * 784 + s * 16 + rV] = vacc[ii];
        }
        __syncthreads();
        // ---- G-phase split across half-lanes: t<8 -> j 0..3, t>=8 -> j 4..7 ----
        {
            const int d8 = t & 7;
            const int jb = (t >> 3) * 4;
#pragma unroll
            for (int jj = 0; jj < 4; jj++) {
                const int j = jb + jj;
                if (j < np) {
                    float q2 = sh[SM_QB + ls * 64 + j * 8 + d8];
                    const float4* kr = reinterpret_cast<const float4*>(&sh[SM_KB + ls * 64 + j * 8]);
                    float4 k0 = kr[0], k1 = kr[1];
                    S2[0] = fmaf(q2, k0.x, S2[0]); S2[1] = fmaf(q2, k0.y, S2[1]);
                    S2[2] = fmaf(q2, k0.z, S2[2]); S2[3] = fmaf(q2, k0.w, S2[3]);
                    S2[4] = fmaf(q2, k1.x, S2[4]); S2[5] = fmaf(q2, k1.y, S2[5]);
                    S2[6] = fmaf(q2, k1.z, S2[6]); S2[7] = fmaf(q2, k1.w, S2[7]);
                }
            }
        }
    }
    // combine half-lane gram partials: lane t gets lane t^8's partial (same sample)
#pragma unroll
    for (int e = 0; e < 8; e++) S2[e] += __shfl_xor_sync(0xffffffffu, S2[e], 8);

    // ---------------- A2: tok3 (grouped, in place, t<8 computes) ----------------
#pragma unroll 1
    for (int sb = 0; sb < 49; sb += 7) {
        float a[7];
#pragma unroll
        for (int u2 = 0; u2 < 7; u2++) {
            float acc = 0.f;
            if (t < 8) {
                const float4* vr = reinterpret_cast<const float4*>(&myrow[(sb + u2) * 16]);
                float4 v0 = vr[0], v1 = vr[1];
                acc = fmaf(S2[0], v0.x, acc); acc = fmaf(S2[1], v0.y, acc);
                acc = fmaf(S2[2], v0.z, acc); acc = fmaf(S2[3], v0.w, acc);
                acc = fmaf(S2[4], v1.x, acc); acc = fmaf(S2[5], v1.y, acc);
                acc = fmaf(S2[6], v1.z, acc); acc = fmaf(S2[7], v1.w, acc);
            }
            a[u2] = acc;
        }
        __syncwarp();
        if (t < 8) {
#pragma unroll
            for (int u2 = 0; u2 < 7; u2++) myrow[(sb + u2) * 16 + t] = a[u2];
        }
        __syncwarp();
    }

    // ---------------- softmax2 ----------------
#pragma unroll 1
    for (int s = t; s < 49; s += 16) {
        float4* row = reinterpret_cast<float4*>(&myrow[s * 16]);
        float4 r0 = row[0], r1 = row[1];
        float m = fmaxf(fmaxf(fmaxf(r0.x, r0.y), fmaxf(r0.z, r0.w)),
                        fmaxf(fmaxf(r1.x, r1.y), fmaxf(r1.z, r1.w)));
        r0.x = __expf(r0.x - m); r0.y = __expf(r0.y - m); r0.z = __expf(r0.z - m); r0.w = __expf(r0.w - m);
        r1.x = __expf(r1.x - m); r1.y = __expf(r1.y - m); r1.z = __expf(r1.z - m); r1.w = __expf(r1.w - m);
        float sum = (r0.x + r0.y + r0.z + r0.w) + (r1.x + r1.y + r1.z + r1.w);
        float inv = 1.f / sum;
        r0.x *= inv; r0.y *= inv; r0.z *= inv; r0.w *= inv;
        r1.x *= inv; r1.y *= inv; r1.z *= inv; r1.w *= inv;
        row[0] = r0; row[1] = r1;
    }

    // ---------------- FC head: fc1w staged in TWO K-halves (stride 200) ----------------
    float acc = sh[SM_F1B + t];
    __syncthreads();
    for (int idx = tid; idx < 768; idx += NTHR) {    // 16 rows x 48 float4 (cols 0..191)
        int j = idx / 48, c4 = idx - j * 48;
        *reinterpret_cast<float4*>(&sh[SM_QB + j * 200 + c4 * 4]) =
            *reinterpret_cast<const float4*>(&fc1w[j * 392 + c4 * 4]);
    }
    __syncthreads();
#pragma unroll 1
    for (int s = 0; s < 24; s++) {
        float4 a0 = *reinterpret_cast<const float4*>(&myrow[s * 16]);
        float4 a1 = *reinterpret_cast<const float4*>(&myrow[s * 16 + 4]);
        float4 w0 = *reinterpret_cast<const float4*>(&sh[SM_QB + t * 200 + s * 8]);
        float4 w1 = *reinterpret_cast<const float4*>(&sh[SM_QB + t * 200 + s * 8 + 4]);
        acc = dot4(w0, a0, acc);
        acc = dot4(w1, a1, acc);
    }
    __syncthreads();
    for (int idx = tid; idx < 800; idx += NTHR) {    // 16 rows x 50 float4 (cols 192..391)
        int j = idx / 50, c4 = idx - j * 50;
        *reinterpret_cast<float4*>(&sh[SM_QB + j * 200 + c4 * 4]) =
            *reinterpret_cast<const float4*>(&fc1w[j * 392 + 192 + c4 * 4]);
    }
    __syncthreads();
#pragma unroll 1
    for (int s = 24; s < 49; s++) {
        float4 a0 = *reinterpret_cast<const float4*>(&myrow[s * 16]);
        float4 a1 = *reinterpret_cast<const float4*>(&myrow[s * 16 + 4]);
        float4 w0 = *reinterpret_cast<const float4*>(&sh[SM_QB + t * 200 + (s - 24) * 8]);
        float4 w1 = *reinterpret_cast<const float4*>(&sh[SM_QB + t * 200 + (s - 24) * 8 + 4]);
        acc = dot4(w0, a0, acc);
        acc = dot4(w1, a1, acc);
    }
    sh[SM_H + ls * 16 + t] = fmaxf(acc, 0.f);
    __syncwarp();

    {
        float lg = 0.f;
        if (t < 10) {
            const float4* w  = reinterpret_cast<const float4*>(&sh[SM_F2W + t * 16]);
            const float4* hh = reinterpret_cast<const float4*>(&sh[SM_H + ls * 16]);
            lg = dot4(w[0], hh[0], lg); lg = dot4(w[1], hh[1], lg);
            lg = dot4(w[2], hh[2], lg); lg = dot4(w[3], hh[3], lg);
            lg += sh[SM_F2B + t];
        }
        sh[SM_LG + ls * 16 + t] = lg;
    }
    __syncwarp();

    if (t == 0 && b < B) {
        const float* lrow = &sh[SM_LG + ls * 16];
        float m = lrow[0];
#pragma unroll
        for (int c = 1; c < 10; c++) m = fmaxf(m, lrow[c]);
        float ex[10], sum = 0.f;
#pragma unroll
        for (int c = 0; c < 10; c++) { ex[c] = __expf(lrow[c] - m); sum += ex[c]; }
        float inv = 1.f / sum;
        float* o = out + (size_t)b * 10;
#pragma unroll
        for (int c = 0; c < 10; c++) o[c] = ex[c] * inv;
    }
}

extern "C" void kernel_launch(void* const* d_in, const int* in_sizes, int n_in,
                              void* d_out, int out_size) {
    const float* x   = (const float*)d_in[0];
    const float* pe  = (const float*)d_in[1];
    const float* WQ1 = (const float*)d_in[2];
    const float* WK1 = (const float*)d_in[3];
    const float* WV1 = (const float*)d_in[4];
    const float* WQ2 = (const float*)d_in[5];
    const float* WK2 = (const float*)d_in[6];
    const float* WV2 = (const float*)d_in[7];
    const float* f1w = (const float*)d_in[8];
    const float* f1b = (const float*)d_in[9];
    const float* f2w = (const float*)d_in[10];
    const float* f2b = (const float*)d_in[11];
    float* out = (float*)d_out;

    int B = in_sizes[0] / (3 * 28 * 28);
    int grid = (B + GRP - 1) / GRP;
    size_t smem = (size_t)SM_TOT * sizeof(float);

    cudaFuncSetAttribute(vit_fused_kernel,
                         cudaFuncAttributeMaxDynamicSharedMemorySize, (int)smem);
    vit_fused_kernel<<<grid, NTHR, smem>>>(x, pe, WQ1, WK1, WV1, WQ2, WK2, WV2,
                                           f1w, f1b, f2w, f2b, out, B);
}